// round 4
// baseline (speedup 1.0000x reference)
#include <cuda_runtime.h>
#include <math.h>

#define HH 512
#define WW 512
#define NG 10000
#define NVIEWS 4
#define PATCH_HALF 20   // off = -20 .. 19
#define TPG 8           // threads cooperating per (view, gaussian)
#define NWORK (NVIEWS * NG)
#define NPIX (NVIEWS * HH * WW)

// per-(view,gaussian) record: 3 x float4
//  rec[0] = {uvx, uvy, iA, iB}
//  rec[1] = {iC, w0, w1, w2}
//  rec[2] = {xy0 packed (x0|y0<<16), nx, cnt, magic}  (int bits)
__device__ float4 g_rec[NWORK * 3];

// float4-per-pixel accumulation scratch (16B aligned -> single red.v4 per hit)
__device__ float4 g_accum[NPIX];

__global__ void __launch_bounds__(256) setup_kernel(
    const float* __restrict__ poses,      // (4,4,4)
    const float* __restrict__ K,          // (3,3)
    const float* __restrict__ means,      // (N,3)
    const float* __restrict__ log_scales, // (N,3)
    const float* __restrict__ quats,      // (N,4)
    const float* __restrict__ shs,        // (N,3,16)
    const float* __restrict__ opac)       // (N,1)
{
    int tid = blockIdx.x * blockDim.x + threadIdx.x;
    int nth = gridDim.x * blockDim.x;

    // zero the float4 accumulation scratch (grid-stride, full grid => full BW)
    for (int i = tid; i < NPIX; i += nth) g_accum[i] = make_float4(0.f, 0.f, 0.f, 0.f);

    int work = tid;
    if (work >= NWORK) return;
    int view = work / NG;
    int n    = work - view * NG;

    float4 r0 = make_float4(0.f, 0.f, 0.f, 0.f);
    float4 r1 = make_float4(0.f, 0.f, 0.f, 0.f);
    float4 r2;
    r2.x = __int_as_float(0);
    r2.y = __int_as_float(1);
    r2.z = __int_as_float(0);   // cnt = 0 default (invalid)
    r2.w = __int_as_float(0);

    float mx = means[n * 3 + 0];
    float my = means[n * 3 + 1];
    float mz = means[n * 3 + 2];

    const float* P = poses + view * 16;
    float pcx = P[0] * mx + P[1] * my + P[2]  * mz + P[3];
    float pcy = P[4] * mx + P[5] * my + P[6]  * mz + P[7];
    float pcz = P[8] * mx + P[9] * my + P[10] * mz + P[11];

    bool ok = (pcz >= 0.1f);

    float ppx = K[0] * pcx + K[1] * pcy + K[2] * pcz;
    float ppy = K[3] * pcx + K[4] * pcy + K[5] * pcz;
    float ppz = K[6] * pcx + K[7] * pcy + K[8] * pcz;

    float zd  = ppz + 1e-8f;
    float uvx = fdividef(ppx, zd);
    float uvy = fdividef(ppy, zd);

    ok = ok && (uvx > -1.f && uvx < (float)WW && uvy > -1.f && uvy < (float)HH);

    if (ok) {
        int u = (int)uvx;   // trunc; in [0,511]
        int v = (int)uvy;

        float s0 = __expf(log_scales[n * 3 + 0]);
        float s1 = __expf(log_scales[n * 3 + 1]);
        float s2 = __expf(log_scales[n * 3 + 2]);

        float qw = quats[n * 4 + 0];
        float qx = quats[n * 4 + 1];
        float qy = quats[n * 4 + 2];
        float qz = quats[n * 4 + 3];

        float R00 = 1.f - 2.f * (qy * qy + qz * qz);
        float R01 = 2.f * (qx * qy - qw * qz);
        float R02 = 2.f * (qx * qz + qw * qy);
        float R10 = 2.f * (qx * qy + qw * qz);
        float R11 = 1.f - 2.f * (qx * qx + qz * qz);
        float R12 = 2.f * (qy * qz - qw * qx);

        float a = s0 * R00 * R00 + s1 * R01 * R01 + s2 * R02 * R02;
        float b = s0 * R00 * R10 + s1 * R01 * R11 + s2 * R02 * R12;
        float d = s0 * R10 * R10 + s1 * R11 * R11 + s2 * R12 * R12;
        float det = a * d - b * b;
        float invdet = fdividef(1.f, det);
        float iA = d * invdet;
        float iB = -b * invdet;
        float iC = a * invdet;

        float op = fdividef(1.f, 1.f + __expf(-opac[n]));
        float w0 = fdividef(op, 1.f + __expf(-shs[n * 48 + 0 * 16]));
        float w1 = fdividef(op, 1.f + __expf(-shs[n * 48 + 1 * 16]));
        float w2 = fdividef(op, 1.f + __expf(-shs[n * 48 + 2 * 16]));

        // conservative ellipse bbox; exact g>0.001 test is reapplied per pixel
        const float QM = 14.2f;
        float rx = sqrtf(QM * a);
        float ry = sqrtf(QM * d);

        float fracx = uvx - (float)u;
        float fracy = uvy - (float)v;

        int ox_lo = (int)ceilf(fracx - rx);
        int ox_hi = (int)floorf(fracx + rx);
        int oy_lo = (int)ceilf(fracy - ry);
        int oy_hi = (int)floorf(fracy + ry);

        ox_lo = max(ox_lo, max(-PATCH_HALF, -u));
        ox_hi = min(ox_hi, min(PATCH_HALF - 1, WW - 1 - u));
        oy_lo = max(oy_lo, max(-PATCH_HALF, -v));
        oy_hi = min(oy_hi, min(PATCH_HALF - 1, HH - 1 - v));

        int nx = ox_hi - ox_lo + 1;
        int ny = oy_hi - oy_lo + 1;
        int cnt = (nx > 0 && ny > 0) ? nx * ny : 0;

        if (cnt > 0) {
            unsigned magic = 0xFFFFFFFFu / (unsigned)nx + 1u;  // exact div for p,nx < 2^16
            r0 = make_float4(uvx, uvy, iA, iB);
            r1 = make_float4(iC, w0, w1, w2);
            r2.x = __int_as_float((u + ox_lo) | ((v + oy_lo) << 16));
            r2.y = __int_as_float(nx);
            r2.z = __int_as_float(cnt);
            r2.w = __int_as_float((int)magic);
        }
    }

    g_rec[work * 3 + 0] = r0;
    g_rec[work * 3 + 1] = r1;
    g_rec[work * 3 + 2] = r2;
}

__global__ void __launch_bounds__(256) splat_kernel()
{
    int gid  = blockIdx.x * blockDim.x + threadIdx.x;
    int work = gid >> 3;          // / TPG
    int lane = gid & (TPG - 1);
    if (work >= NWORK) return;

    float4 r2 = g_rec[work * 3 + 2];
    int cnt = __float_as_int(r2.z);
    if (lane >= cnt) return;

    float4 r0 = g_rec[work * 3 + 0];
    float4 r1 = g_rec[work * 3 + 1];

    float uvx = r0.x, uvy = r0.y, iA = r0.z, iB = r0.w;
    float iC  = r1.x, w0 = r1.y, w1 = r1.z, w2 = r1.w;
    int xy0   = __float_as_int(r2.x);
    int nx    = __float_as_int(r2.y);
    unsigned magic = (unsigned)__float_as_int(r2.w);
    int x0 = xy0 & 0xFFFF;
    int y0 = xy0 >> 16;

    int view = work / NG;
    float4* img = g_accum + (size_t)view * HH * WW;

    for (int p = lane; p < cnt; p += TPG) {
        int oyi = (int)__umulhi((unsigned)p, magic);   // p / nx, exact
        int oxi = p - oyi * nx;
        int yy = y0 + oyi;
        int xx = x0 + oxi;
        float py = (float)yy - uvy;
        float px = (float)xx - uvx;
        float q = iA * px * px + 2.f * iB * px * py + iC * py * py;
        float expo = -0.5f * q;
        expo = fminf(expo, 0.f);
        expo = fmaxf(expo, -10.f);
        float g = __expf(expo);
        if (g > 0.001f) {
            float4* pix = img + ((size_t)yy * WW + xx);
            asm volatile("red.global.add.v4.f32 [%0], {%1, %2, %3, %4};"
                         :: "l"(pix), "f"(g * w0), "f"(g * w1), "f"(g * w2), "f"(0.f)
                         : "memory");
        }
    }
}

// convert float4-per-pixel scratch into packed (..,3) float output
__global__ void __launch_bounds__(256) merge_kernel(float* __restrict__ out)
{
    int i = blockIdx.x * blockDim.x + threadIdx.x;
    if (i >= NPIX) return;
    float4 v = g_accum[i];
    float* o = out + (size_t)i * 3;
    o[0] = v.x;
    o[1] = v.y;
    o[2] = v.z;
}

extern "C" void kernel_launch(void* const* d_in, const int* in_sizes, int n_in,
                              void* d_out, int out_size) {
    const float* poses      = (const float*)d_in[0];
    const float* intr       = (const float*)d_in[1];
    const float* means      = (const float*)d_in[2];
    const float* log_scales = (const float*)d_in[3];
    const float* quats      = (const float*)d_in[4];
    const float* shs        = (const float*)d_in[5];
    const float* opac       = (const float*)d_in[6];
    float* out = (float*)d_out;

    // big grid: grid-stride zero of 16.8MB scratch + setup for tid < NWORK
    setup_kernel<<<1184, 256>>>(poses, intr, means, log_scales, quats, shs, opac);

    int total = NWORK * TPG;
    splat_kernel<<<(total + 255) / 256, 256>>>();

    merge_kernel<<<(NPIX + 255) / 256, 256>>>(out);
}

// round 5
// speedup vs baseline: 1.5733x; 1.5733x over previous
#include <cuda_runtime.h>
#include <math.h>

#define HH 512
#define WW 512
#define NG 10000
#define NVIEWS 4
#define PATCH_HALF 20   // off = -20 .. 19
#define TPG 4           // threads cooperating per (view, gaussian)
#define NWORK (NVIEWS * NG)

// SoA per-(view,gaussian) records:
//  g_r0 = {uvx, uvy, iA, iB}
//  g_r1 = {iC, w0, w1, w2}
//  g_r2 = {xy0 packed (x0|y0<<16), nx, cnt, magic}  (int bits)
__device__ float4 g_r0[NWORK];
__device__ float4 g_r1[NWORK];
__device__ float4 g_r2[NWORK];

__global__ void __launch_bounds__(256) zero_out_kernel(float4* __restrict__ out, int n4) {
    int i = blockIdx.x * blockDim.x + threadIdx.x;
    int stride = gridDim.x * blockDim.x;
    for (; i < n4; i += stride) out[i] = make_float4(0.f, 0.f, 0.f, 0.f);
}

__global__ void __launch_bounds__(256) setup_kernel(
    const float* __restrict__ poses,      // (4,4,4)
    const float* __restrict__ K,          // (3,3)
    const float* __restrict__ means,      // (N,3)
    const float* __restrict__ log_scales, // (N,3)
    const float* __restrict__ quats,      // (N,4)
    const float* __restrict__ shs,        // (N,3,16)
    const float* __restrict__ opac)       // (N,1)
{
    int work = blockIdx.x * blockDim.x + threadIdx.x;
    if (work >= NWORK) return;
    int view = work / NG;
    int n    = work - view * NG;

    float4 r0 = make_float4(0.f, 0.f, 0.f, 0.f);
    float4 r1 = make_float4(0.f, 0.f, 0.f, 0.f);
    float4 r2;
    r2.x = __int_as_float(0);
    r2.y = __int_as_float(1);
    r2.z = __int_as_float(0);   // cnt = 0 default (invalid)
    r2.w = __int_as_float(0);

    float mx = means[n * 3 + 0];
    float my = means[n * 3 + 1];
    float mz = means[n * 3 + 2];

    const float* P = poses + view * 16;
    float pcx = P[0] * mx + P[1] * my + P[2]  * mz + P[3];
    float pcy = P[4] * mx + P[5] * my + P[6]  * mz + P[7];
    float pcz = P[8] * mx + P[9] * my + P[10] * mz + P[11];

    bool ok = (pcz >= 0.1f);

    float ppx = K[0] * pcx + K[1] * pcy + K[2] * pcz;
    float ppy = K[3] * pcx + K[4] * pcy + K[5] * pcz;
    float ppz = K[6] * pcx + K[7] * pcy + K[8] * pcz;

    float zd  = ppz + 1e-8f;
    float uvx = fdividef(ppx, zd);
    float uvy = fdividef(ppy, zd);

    ok = ok && (uvx > -1.f && uvx < (float)WW && uvy > -1.f && uvy < (float)HH);

    if (ok) {
        int u = (int)uvx;   // trunc; in [0,511]
        int v = (int)uvy;

        float s0 = __expf(log_scales[n * 3 + 0]);
        float s1 = __expf(log_scales[n * 3 + 1]);
        float s2 = __expf(log_scales[n * 3 + 2]);

        float qw = quats[n * 4 + 0];
        float qx = quats[n * 4 + 1];
        float qy = quats[n * 4 + 2];
        float qz = quats[n * 4 + 3];

        float R00 = 1.f - 2.f * (qy * qy + qz * qz);
        float R01 = 2.f * (qx * qy - qw * qz);
        float R02 = 2.f * (qx * qz + qw * qy);
        float R10 = 2.f * (qx * qy + qw * qz);
        float R11 = 1.f - 2.f * (qx * qx + qz * qz);
        float R12 = 2.f * (qy * qz - qw * qx);

        float a = s0 * R00 * R00 + s1 * R01 * R01 + s2 * R02 * R02;
        float b = s0 * R00 * R10 + s1 * R01 * R11 + s2 * R02 * R12;
        float d = s0 * R10 * R10 + s1 * R11 * R11 + s2 * R12 * R12;
        float det = a * d - b * b;
        float invdet = fdividef(1.f, det);
        float iA = d * invdet;
        float iB = -b * invdet;
        float iC = a * invdet;

        float op = fdividef(1.f, 1.f + __expf(-opac[n]));
        float w0 = fdividef(op, 1.f + __expf(-shs[n * 48 + 0 * 16]));
        float w1 = fdividef(op, 1.f + __expf(-shs[n * 48 + 1 * 16]));
        float w2 = fdividef(op, 1.f + __expf(-shs[n * 48 + 2 * 16]));

        // conservative ellipse bbox; exact g>0.001 test is reapplied per pixel
        const float QM = 14.2f;
        float rx = sqrtf(QM * a);
        float ry = sqrtf(QM * d);

        float fracx = uvx - (float)u;
        float fracy = uvy - (float)v;

        int ox_lo = (int)ceilf(fracx - rx);
        int ox_hi = (int)floorf(fracx + rx);
        int oy_lo = (int)ceilf(fracy - ry);
        int oy_hi = (int)floorf(fracy + ry);

        ox_lo = max(ox_lo, max(-PATCH_HALF, -u));
        ox_hi = min(ox_hi, min(PATCH_HALF - 1, WW - 1 - u));
        oy_lo = max(oy_lo, max(-PATCH_HALF, -v));
        oy_hi = min(oy_hi, min(PATCH_HALF - 1, HH - 1 - v));

        int nx = ox_hi - ox_lo + 1;
        int ny = oy_hi - oy_lo + 1;
        int cnt = (nx > 0 && ny > 0) ? nx * ny : 0;

        if (cnt > 0) {
            unsigned magic = 0xFFFFFFFFu / (unsigned)nx + 1u;  // exact div for p,nx < 2^16
            r0 = make_float4(uvx, uvy, iA, iB);
            r1 = make_float4(iC, w0, w1, w2);
            r2.x = __int_as_float((u + ox_lo) | ((v + oy_lo) << 16));
            r2.y = __int_as_float(nx);
            r2.z = __int_as_float(cnt);
            r2.w = __int_as_float((int)magic);
        }
    }

    g_r0[work] = r0;
    g_r1[work] = r1;
    g_r2[work] = r2;
}

__global__ void __launch_bounds__(256) splat_kernel(float* __restrict__ out)
{
    int gid  = blockIdx.x * blockDim.x + threadIdx.x;
    int work = gid >> 2;          // / TPG
    int lane = gid & (TPG - 1);
    if (work >= NWORK) return;

    // issue all three loads up-front (MLP=3, warp covers 8 consecutive float4s = 128B line each)
    float4 r2 = g_r2[work];
    float4 r0 = g_r0[work];
    float4 r1 = g_r1[work];

    int cnt = __float_as_int(r2.z);
    if (lane >= cnt) return;

    float uvx = r0.x, uvy = r0.y, iA = r0.z, iB = r0.w;
    float iC  = r1.x, w0 = r1.y, w1 = r1.z, w2 = r1.w;
    int xy0   = __float_as_int(r2.x);
    int nx    = __float_as_int(r2.y);
    unsigned magic = (unsigned)__float_as_int(r2.w);
    int x0 = xy0 & 0xFFFF;
    int y0 = xy0 >> 16;

    int view = work / NG;
    float* img = out + (size_t)view * HH * WW * 3;

    for (int p = lane; p < cnt; p += TPG) {
        int oyi = (int)__umulhi((unsigned)p, magic);   // p / nx, exact
        int oxi = p - oyi * nx;
        int yy = y0 + oyi;
        int xx = x0 + oxi;
        float py = (float)yy - uvy;
        float px = (float)xx - uvx;
        float q = iA * px * px + 2.f * iB * px * py + iC * py * py;
        float expo = -0.5f * q;
        expo = fminf(expo, 0.f);
        expo = fmaxf(expo, -10.f);
        float g = __expf(expo);
        if (g > 0.001f) {
            float* pix = img + ((size_t)yy * WW + xx) * 3;
            atomicAdd(pix + 0, g * w0);
            atomicAdd(pix + 1, g * w1);
            atomicAdd(pix + 2, g * w2);
        }
    }
}

extern "C" void kernel_launch(void* const* d_in, const int* in_sizes, int n_in,
                              void* d_out, int out_size) {
    const float* poses      = (const float*)d_in[0];
    const float* intr       = (const float*)d_in[1];
    const float* means      = (const float*)d_in[2];
    const float* log_scales = (const float*)d_in[3];
    const float* quats      = (const float*)d_in[4];
    const float* shs        = (const float*)d_in[5];
    const float* opac       = (const float*)d_in[6];
    float* out = (float*)d_out;

    int n4 = out_size / 4;   // 786432 float4s
    zero_out_kernel<<<768, 256>>>((float4*)out, n4);

    setup_kernel<<<(NWORK + 255) / 256, 256>>>(
        poses, intr, means, log_scales, quats, shs, opac);

    int total = NWORK * TPG;
    splat_kernel<<<(total + 255) / 256, 256>>>(out);
}

// round 6
// speedup vs baseline: 1.8627x; 1.1839x over previous
#include <cuda_runtime.h>
#include <math.h>

#define HH 512
#define WW 512
#define NG 10000
#define NVIEWS 4
#define PATCH_HALF 20   // off = -20 .. 19
#define TPG 4           // threads cooperating per (view, gaussian)
#define NWORK (NVIEWS * NG)
#define GPB 64          // gaussians (work items) per block
#define NBLK (NWORK / GPB)   // 625, exact

__global__ void __launch_bounds__(256) zero_out_kernel(float4* __restrict__ out) {
    int i = blockIdx.x * blockDim.x + threadIdx.x;
    out[i] = make_float4(0.f, 0.f, 0.f, 0.f);   // grid sized exactly: no bound check
}

__global__ void __launch_bounds__(256) fused_kernel(
    const float* __restrict__ poses,      // (4,4,4)
    const float* __restrict__ K,          // (3,3)
    const float* __restrict__ means,      // (N,3)
    const float* __restrict__ log_scales, // (N,3)
    const float* __restrict__ quats,      // (N,4)
    const float* __restrict__ shs,        // (N,3,16)
    const float* __restrict__ opac,       // (N,1)
    float* __restrict__ out)              // (4,512,512,3)
{
    // per-block records for GPB gaussians:
    //  s_r0 = {uvx, uvy, iA, iB}
    //  s_r1 = {iC, w0, w1, w2}
    //  s_r2 = {x0, y0, nx, cnt} (int bits)
    __shared__ float4 s_r0[GPB];
    __shared__ float4 s_r1[GPB];
    __shared__ float4 s_r2[GPB];

    int tid = threadIdx.x;

    // ---------------- phase 1: setup (threads 0..GPB-1) ----------------
    if (tid < GPB) {
        int work = blockIdx.x * GPB + tid;   // < NWORK by construction
        int view = work / NG;
        int n    = work - view * NG;

        float4 r0 = make_float4(0.f, 0.f, 0.f, 0.f);
        float4 r1 = make_float4(0.f, 0.f, 0.f, 0.f);
        float4 r2;
        r2.x = __int_as_float(0);
        r2.y = __int_as_float(0);
        r2.z = __int_as_float(1);
        r2.w = __int_as_float(0);   // cnt = 0 default (invalid)

        float mx = means[n * 3 + 0];
        float my = means[n * 3 + 1];
        float mz = means[n * 3 + 2];

        const float* P = poses + view * 16;
        float pcx = P[0] * mx + P[1] * my + P[2]  * mz + P[3];
        float pcy = P[4] * mx + P[5] * my + P[6]  * mz + P[7];
        float pcz = P[8] * mx + P[9] * my + P[10] * mz + P[11];

        bool ok = (pcz >= 0.1f);

        float ppx = K[0] * pcx + K[1] * pcy + K[2] * pcz;
        float ppy = K[3] * pcx + K[4] * pcy + K[5] * pcz;
        float ppz = K[6] * pcx + K[7] * pcy + K[8] * pcz;

        float zd  = ppz + 1e-8f;
        float uvx = fdividef(ppx, zd);
        float uvy = fdividef(ppy, zd);

        ok = ok && (uvx > -1.f && uvx < (float)WW && uvy > -1.f && uvy < (float)HH);

        if (ok) {
            int u = (int)uvx;   // trunc; in [0,511]
            int v = (int)uvy;

            float s0 = __expf(log_scales[n * 3 + 0]);
            float s1 = __expf(log_scales[n * 3 + 1]);
            float s2 = __expf(log_scales[n * 3 + 2]);

            float qw = quats[n * 4 + 0];
            float qx = quats[n * 4 + 1];
            float qy = quats[n * 4 + 2];
            float qz = quats[n * 4 + 3];

            float R00 = 1.f - 2.f * (qy * qy + qz * qz);
            float R01 = 2.f * (qx * qy - qw * qz);
            float R02 = 2.f * (qx * qz + qw * qy);
            float R10 = 2.f * (qx * qy + qw * qz);
            float R11 = 1.f - 2.f * (qx * qx + qz * qz);
            float R12 = 2.f * (qy * qz - qw * qx);

            float a = s0 * R00 * R00 + s1 * R01 * R01 + s2 * R02 * R02;
            float b = s0 * R00 * R10 + s1 * R01 * R11 + s2 * R02 * R12;
            float d = s0 * R10 * R10 + s1 * R11 * R11 + s2 * R12 * R12;
            float det = a * d - b * b;
            float invdet = fdividef(1.f, det);
            float iA = d * invdet;
            float iB = -b * invdet;
            float iC = a * invdet;

            float op = fdividef(1.f, 1.f + __expf(-opac[n]));
            float w0 = fdividef(op, 1.f + __expf(-shs[n * 48 + 0 * 16]));
            float w1 = fdividef(op, 1.f + __expf(-shs[n * 48 + 1 * 16]));
            float w2 = fdividef(op, 1.f + __expf(-shs[n * 48 + 2 * 16]));

            // conservative ellipse bbox; exact g>0.001 test reapplied per pixel
            const float QM = 14.2f;
            float rx = sqrtf(QM * a);
            float ry = sqrtf(QM * d);

            float fracx = uvx - (float)u;
            float fracy = uvy - (float)v;

            int ox_lo = (int)ceilf(fracx - rx);
            int ox_hi = (int)floorf(fracx + rx);
            int oy_lo = (int)ceilf(fracy - ry);
            int oy_hi = (int)floorf(fracy + ry);

            ox_lo = max(ox_lo, max(-PATCH_HALF, -u));
            ox_hi = min(ox_hi, min(PATCH_HALF - 1, WW - 1 - u));
            oy_lo = max(oy_lo, max(-PATCH_HALF, -v));
            oy_hi = min(oy_hi, min(PATCH_HALF - 1, HH - 1 - v));

            int nx = ox_hi - ox_lo + 1;
            int ny = oy_hi - oy_lo + 1;
            int cnt = (nx > 0 && ny > 0) ? nx * ny : 0;

            if (cnt > 0) {
                r0 = make_float4(uvx, uvy, iA, iB);
                r1 = make_float4(iC, w0, w1, w2);
                r2.x = __int_as_float(u + ox_lo);
                r2.y = __int_as_float(v + oy_lo);
                r2.z = __int_as_float(nx);
                r2.w = __int_as_float(cnt);
            }
        }

        s_r0[tid] = r0;
        s_r1[tid] = r1;
        s_r2[tid] = r2;
    }

    __syncthreads();

    // ---------------- phase 2: splat (all 256 threads, TPG=4) ----------------
    int g    = tid >> 2;          // 0..63
    int lane = tid & (TPG - 1);

    float4 r2 = s_r2[g];
    int cnt = __float_as_int(r2.w);
    if (lane >= cnt) return;

    float4 r0 = s_r0[g];
    float4 r1 = s_r1[g];

    float uvx = r0.x, uvy = r0.y, iA = r0.z, iB = r0.w;
    float iC  = r1.x, w0 = r1.y, w1 = r1.z, w2 = r1.w;
    int x0 = __float_as_int(r2.x);
    int y0 = __float_as_int(r2.y);
    int nx = __float_as_int(r2.z);

    int work = blockIdx.x * GPB + g;
    int view = work / NG;
    float* img = out + (size_t)view * HH * WW * 3;

    for (int p = lane; p < cnt; p += TPG) {
        // nx is 2..4 typically; p < ~36. cheap exact div via float is risky; use int ops
        int oyi = p / nx;              // small ints: compiler emits fast sequence
        int oxi = p - oyi * nx;
        int yy = y0 + oyi;
        int xx = x0 + oxi;
        float py = (float)yy - uvy;
        float px = (float)xx - uvx;
        float q = iA * px * px + 2.f * iB * px * py + iC * py * py;
        float expo = -0.5f * q;
        expo = fminf(expo, 0.f);
        expo = fmaxf(expo, -10.f);
        float gg = __expf(expo);
        if (gg > 0.001f) {
            float* pix = img + ((size_t)yy * WW + xx) * 3;
            atomicAdd(pix + 0, gg * w0);
            atomicAdd(pix + 1, gg * w1);
            atomicAdd(pix + 2, gg * w2);
        }
    }
}

extern "C" void kernel_launch(void* const* d_in, const int* in_sizes, int n_in,
                              void* d_out, int out_size) {
    const float* poses      = (const float*)d_in[0];
    const float* intr       = (const float*)d_in[1];
    const float* means      = (const float*)d_in[2];
    const float* log_scales = (const float*)d_in[3];
    const float* quats      = (const float*)d_in[4];
    const float* shs        = (const float*)d_in[5];
    const float* opac       = (const float*)d_in[6];
    float* out = (float*)d_out;

    int n4 = out_size / 4;                 // 786432 float4s, divisible by 256
    zero_out_kernel<<<n4 / 256, 256>>>((float4*)out);

    fused_kernel<<<NBLK, 256>>>(poses, intr, means, log_scales, quats, shs, opac, out);
}